// round 1
// baseline (speedup 1.0000x reference)
#include <cuda_runtime.h>
#include <math.h>

#define Bc 16
#define Nc 127
#define Sc 32
#define Ec 16
#define Vc 128
#define BTc 2048

// scratch (no allocations allowed)
__device__ float g_xbuf[BTc * Ec];     // u + o per bt
__device__ float g_ret[BTc * Vc];      // pre-combine logits

// ---------------------------------------------------------------------------
// Kernel 1: everything up to (u + o) per bt row.
// grid = 512 CTAs x 256 threads, each CTA handles 4 bt rows.
// ---------------------------------------------------------------------------
__global__ __launch_bounds__(256) void memnet_main(
    const float* __restrict__ node_fts,   // [B,N,S]
    const float* __restrict__ edge_fts,   // [B,N,N,S]
    const float* __restrict__ graph_fts,  // [B,S]
    const float* __restrict__ adj,        // [B,N,N]
    const float* __restrict__ enc,        // [S,E]
    const float* __restrict__ qb_g,       // [V-1,E]
    const float* __restrict__ sb_g,       // [V-1,E]
    const float* __restrict__ ob_g,       // [V-1,E]
    const float* __restrict__ mc_g)       // [M=128,E]
{
    extern __shared__ char smem[];
    float* sbT    = (float*)smem;          // [16][128] transposed (bank-friendly)
    float* obS    = sbT + 2048;            // [128][16]
    float* qbS    = obS + 2048;            // [128][16]
    float* mcT    = qbS + 2048;            // [16][128] transposed
    float* encS   = mcT + 2048;            // [32][16]
    float* eu     = encS + 512;            // [32][16]  enc*u
    float* G      = eu + 512;              // [32][128] score lookup table
    float* wS     = G + 4096;              // [32][128] probs histogram
    float* t2     = wS + 4096;             // [32][16]
    float* uvec   = t2 + 512;              // [16]
    float* scores = uvec + 16;             // [128]
    float* probs  = scores + 128;          // [128]
    float* red    = probs + 128;           // [16]
    int*   qs     = (int*)(red + 16);      // [32]
    unsigned char* sidx = (unsigned char*)(qs + 32);  // [128*32]

    const int tid = threadIdx.x;

    // load tables once per CTA
    for (int i = tid; i < 2048; i += 256) {
        int v = i >> 4, e = i & 15;
        sbT[e * 128 + v] = (v < Nc) ? sb_g[i] : 0.f;   // row V-1 is the nil row
        obS[i]           = (v < Nc) ? ob_g[i] : 0.f;
        qbS[i]           = (v < Nc) ? qb_g[i] : 0.f;
        mcT[e * 128 + v] = mc_g[i];
    }
    for (int i = tid; i < 512; i += 256) encS[i] = enc[i];
    __syncthreads();

    const int vv   = tid & 127;
    const int sg   = tid >> 7;       // 0..1: s-group for G build
    const int m    = tid >> 1;       // memory slot this thread pair owns
    const int half = tid & 1;        // which 16 of the 32 sentence slots
    const int lane = tid & 31, wid = tid >> 5;

    float sv[16], mcv[16];
#pragma unroll
    for (int e = 0; e < 16; e++) sv[e] = sbT[e * 128 + vv];
#pragma unroll
    for (int e = 0; e < 16; e++) mcv[e] = mcT[e * 128 + m];

    for (int r = 0; r < 4; r++) {
        const int bt = blockIdx.x * 4 + r;
        const int b = bt >> 7, t = bt & 127;

        // --- query indices & u[e] = sum_s qb[qidx[s],e]*enc[s,e] ---
        if (tid < 32) {
            float qv = (t < Nc) ? node_fts[(b * Nc + t) * Sc + tid]
                                : graph_fts[b * Sc + tid];
            int qi = (int)qv;
            qi = qi < 0 ? 0 : (qi > 127 ? 127 : qi);
            qs[tid] = qi;
        }
        __syncthreads();
        if (tid < 16) {
            float acc = 0.f;
#pragma unroll
            for (int s = 0; s < 32; s++)
                acc += qbS[qs[s] * 16 + tid] * encS[s * 16 + tid];
            uvec[tid] = acc;
        }
        __syncthreads();
        for (int i = tid; i < 512; i += 256) eu[i] = encS[i] * uvec[i & 15];
        for (int i = tid; i < 4096; i += 256) wS[i] = 0.f;
        __syncthreads();

        // --- build G[s][v] = dot(sb[v,:], eu[s,:]) ---
#pragma unroll
        for (int k = 0; k < 16; k++) {
            int s = sg * 16 + k;
            float acc = 0.f;
#pragma unroll
            for (int e = 0; e < 16; e++) acc += sv[e] * eu[s * 16 + e];
            G[s * 128 + vv] = acc;
        }
        __syncthreads();

        // --- scores via table lookups; single coalesced edge_fts pass ---
        float acc = 0.f;
        const bool valid = (t < Nc) && (m < Nc);
        if (valid) {
            const float* erow =
                edge_fts + ((size_t)((b * Nc + t) * Nc + m)) * Sc + half * 16;
            float a = adj[(b * Nc + t) * Nc + m];
            float4 x0 = ((const float4*)erow)[0];
            float4 x1 = ((const float4*)erow)[1];
            float4 x2 = ((const float4*)erow)[2];
            float4 x3 = ((const float4*)erow)[3];
            float vals[16] = {x0.x, x0.y, x0.z, x0.w, x1.x, x1.y, x1.z, x1.w,
                              x2.x, x2.y, x2.z, x2.w, x3.x, x3.y, x3.z, x3.w};
            const bool am = (a != 0.f);
#pragma unroll
            for (int k = 0; k < 16; k++) {
                int idx = am ? (int)vals[k] : 0;
                idx = idx < 0 ? 0 : (idx > 127 ? 127 : idx);
                sidx[m * 32 + half * 16 + k] = (unsigned char)idx;
                acc += G[(half * 16 + k) * 128 + idx];
            }
        } else {
#pragma unroll
            for (int k = 0; k < 16; k++) {
                sidx[m * 32 + half * 16 + k] = 0;
                acc += G[(half * 16 + k) * 128];
            }
        }
        acc += __shfl_xor_sync(0xFFFFFFFFu, acc, 1);
        if (half == 0) {
            float d = 0.f;
#pragma unroll
            for (int e = 0; e < 16; e++) d += mcv[e] * uvec[e];
            scores[m] = acc + d;
        }
        __syncthreads();

        // --- softmax over 128 memory slots ---
        {
            float sval = (tid < 128) ? scores[tid] : -1e30f;
            float mv = sval;
#pragma unroll
            for (int off = 16; off; off >>= 1)
                mv = fmaxf(mv, __shfl_xor_sync(0xFFFFFFFFu, mv, off));
            if (lane == 0) red[wid] = mv;
            __syncthreads();
            float mx = red[0];
#pragma unroll
            for (int i2 = 1; i2 < 8; i2++) mx = fmaxf(mx, red[i2]);
            float ex = (tid < 128) ? expf(sval - mx) : 0.f;
            float sm = ex;
#pragma unroll
            for (int off = 16; off; off >>= 1)
                sm += __shfl_xor_sync(0xFFFFFFFFu, sm, off);
            if (lane == 0) red[8 + wid] = sm;
            __syncthreads();
            float tot = red[8];
#pragma unroll
            for (int i2 = 9; i2 < 16; i2++) tot += red[i2];
            if (tid < 128) probs[tid] = ex / tot;
            __syncthreads();
        }

        // --- scatter probs into histogram w[s][v] ---
        {
            float pm = probs[m];
#pragma unroll
            for (int k = 0; k < 16; k++) {
                int s = half * 16 + k;
                atomicAdd(&wS[s * 128 + sidx[m * 32 + s]], pm);
            }
        }
        __syncthreads();

        // --- o[e] = sum_s enc[s,e] * (w[s,:] @ ob[:,e]) ---
#pragma unroll
        for (int p = 0; p < 2; p++) {
            int idx2 = tid + p * 256;
            int s = idx2 >> 4, e = idx2 & 15;
            float accv = 0.f;
#pragma unroll 8
            for (int v2 = 0; v2 < 128; v2++)
                accv += wS[s * 128 + v2] * obS[v2 * 16 + e];
            t2[s * 16 + e] = accv * encS[s * 16 + e];
        }
        __syncthreads();
        if (tid < 16) {
            float oa = 0.f;
#pragma unroll
            for (int s = 0; s < 32; s++) oa += t2[s * 16 + tid];
            g_xbuf[bt * 16 + tid] = uvec[tid] + oa;
        }
        __syncthreads();
    }
}

// ---------------------------------------------------------------------------
// Kernel 2: ret = relu((u+o) @ W_out) @ W_fin, weights in shared.
// ---------------------------------------------------------------------------
__global__ __launch_bounds__(128) void memnet_gemm(
    const float* __restrict__ W_out,   // [16,128]
    const float* __restrict__ W_fin)   // [128,128]
{
    extern __shared__ char smem[];
    float* Wo = (float*)smem;          // 2048
    float* Wf = Wo + 2048;             // 16384
    float* xs = Wf + 16384;            // 16
    float* hs = xs + 16;               // 128

    const int tid = threadIdx.x;
    for (int i = tid; i < 2048; i += 128) Wo[i] = W_out[i];
    for (int i = tid; i < 16384; i += 128) Wf[i] = W_fin[i];
    __syncthreads();

    for (int bt = blockIdx.x; bt < BTc; bt += gridDim.x) {
        if (tid < 16) xs[tid] = g_xbuf[bt * 16 + tid];
        __syncthreads();
        float h = 0.f;
#pragma unroll
        for (int e = 0; e < 16; e++) h += xs[e] * Wo[e * 128 + tid];
        hs[tid] = fmaxf(h, 0.f);
        __syncthreads();
        float acc = 0.f;
#pragma unroll 16
        for (int l = 0; l < 128; l++) acc += hs[l] * Wf[l * 128 + tid];
        g_ret[bt * 128 + tid] = acc;
        __syncthreads();
    }
}

// ---------------------------------------------------------------------------
// Kernel 3: out[b,i,:] = ret[b,i,:] + ret[b,127,:]
// ---------------------------------------------------------------------------
__global__ void memnet_final(float* __restrict__ out)
{
    const int total = Bc * Nc * Vc;   // 260096
    int idx = blockIdx.x * blockDim.x + threadIdx.x;
    if (idx < total) {
        int v = idx & 127;
        int rem = idx >> 7;
        int i = rem % Nc;
        int b = rem / Nc;
        out[idx] = g_ret[((b << 7) + i) * 128 + v] +
                   g_ret[((b << 7) + 127) * 128 + v];
    }
}

extern "C" void kernel_launch(void* const* d_in, const int* in_sizes, int n_in,
                              void* d_out, int out_size)
{
    const float* node_fts  = (const float*)d_in[0];
    const float* edge_fts  = (const float*)d_in[1];
    const float* graph_fts = (const float*)d_in[2];
    const float* adj       = (const float*)d_in[3];
    // d_in[4] hidden: unused
    const float* enc       = (const float*)d_in[5];
    const float* qb        = (const float*)d_in[6];
    const float* sb        = (const float*)d_in[7];
    const float* ob        = (const float*)d_in[8];
    const float* mc        = (const float*)d_in[9];
    // d_in[10] W_int: unused (num_hops == 1)
    const float* W_out     = (const float*)d_in[11];
    const float* W_fin     = (const float*)d_in[12];
    float* out = (float*)d_out;

    const int SM1 = 77056;
    const int SM2 = (2048 + 16384 + 16 + 128) * 4;
    cudaFuncSetAttribute(memnet_main, cudaFuncAttributeMaxDynamicSharedMemorySize, SM1);
    cudaFuncSetAttribute(memnet_gemm, cudaFuncAttributeMaxDynamicSharedMemorySize, SM2);

    memnet_main<<<512, 256, SM1>>>(node_fts, edge_fts, graph_fts, adj, enc,
                                   qb, sb, ob, mc);
    memnet_gemm<<<128, 128, SM2>>>(W_out, W_fin);
    memnet_final<<<(Bc * Nc * Vc + 255) / 256, 256>>>(out);
}

// round 3
// speedup vs baseline: 3.7259x; 3.7259x over previous
#include <cuda_runtime.h>
#include <math.h>

#define Bc 16
#define Nc 127
#define Sc 32
#define Ec 16
#define Vc 128
#define BTc 2048

// scratch (no allocations allowed)
__device__ float g_xbuf[BTc * Ec];     // u + o per bt
__device__ float g_ret[BTc * Vc];      // pre-combine logits

// shared layout (floats)
#define OFF_HIST   0                   // [128][67]  per-(s,mh) private histograms (indexed [v][rep])
#define OFF_G01    (OFF_HIST + 128*67) // float2[128]
#define OFF_UPART  (OFF_G01 + 256)     // [32][33]
#define OFF_SIDX   (OFF_UPART + 1056)  // uint32 [128][8]
#define OFF_U      (OFF_SIDX + 1024)   // [16]
#define OFF_AU     (OFF_U + 16)        // [16]
#define OFF_A      (OFF_AU + 16)       // [16]
#define OFF_B      (OFF_A + 16)        // [32]
#define OFF_PROBS  (OFF_B + 32)        // [128]
#define OFF_RED    (OFF_PROBS + 128)   // [32]
#define SMEM_MAIN  ((OFF_RED + 32) * 4)

// ---------------------------------------------------------------------------
// Kernel 1: one CTA (128 threads) per bt row. Rank-1 enc factorization:
//   enc[s,e] = 1 + B[s]*A[e]   (exact; factors derived from enc input)
// ---------------------------------------------------------------------------
__global__ __launch_bounds__(128) void memnet_main(
    const float* __restrict__ node_fts,   // [B,N,S]
    const float* __restrict__ edge_fts,   // [B,N,N,S]
    const float* __restrict__ graph_fts,  // [B,S]
    const float* __restrict__ adj,        // [B,N,N]
    const float* __restrict__ enc,        // [S,E]
    const float* __restrict__ qb,         // [V-1,E]
    const float* __restrict__ sb,         // [V-1,E]
    const float* __restrict__ ob,         // [V-1,E]
    const float* __restrict__ mc)         // [M=128,E]
{
    extern __shared__ float sm[];
    float*        hist  = sm + OFF_HIST;
    float2*       g01   = (float2*)(sm + OFF_G01);
    float*        upart = sm + OFF_UPART;
    unsigned*     sidxw = (unsigned*)(sm + OFF_SIDX);
    float*        u     = sm + OFF_U;
    float*        Au    = sm + OFF_AU;
    float*        Ash   = sm + OFF_A;
    float*        Bsh   = sm + OFF_B;
    float*        probs = sm + OFF_PROBS;
    float*        red   = sm + OFF_RED;

    const int tid  = threadIdx.x;
    const int lane = tid & 31;
    const int wid  = tid >> 5;
    const int bt   = blockIdx.x;
    const int b    = bt >> 7;
    const int t    = bt & 127;

    // ---- Phase 0: rank-1 factors of enc ----
    if (tid < 16) Ash[tid] = enc[tid] - 1.f;
    if (tid < 32) Bsh[tid] = (enc[tid * 16] - 1.f) / (enc[0] - 1.f);

    // ---- Phase 1: query gather -> u[e] = q0[e] + A[e]*q1[e] ----
    if (tid < 32) {
        float qv = (t < Nc) ? node_fts[(b * Nc + t) * Sc + tid]
                            : graph_fts[b * Sc + tid];
        int qi = (int)qv;
        qi = qi < 0 ? 0 : (qi > 127 ? 127 : qi);
        float r[16];
        if (qi < 127) {
            const float4* qr = (const float4*)(qb + qi * 16);
#pragma unroll
            for (int j = 0; j < 4; j++) {
                float4 x4 = qr[j];
                r[4*j] = x4.x; r[4*j+1] = x4.y; r[4*j+2] = x4.z; r[4*j+3] = x4.w;
            }
        } else {
#pragma unroll
            for (int e = 0; e < 16; e++) r[e] = 0.f;
        }
        float bs = (enc[tid * 16] - 1.f) / (enc[0] - 1.f);
#pragma unroll
        for (int e = 0; e < 16; e++) {
            upart[tid * 33 + e]      = r[e];
            upart[tid * 33 + 16 + e] = bs * r[e];
        }
    }
    __syncthreads();
    if (tid < 32) {
        float acc = 0.f;
#pragma unroll
        for (int s = 0; s < 32; s++) acc += upart[s * 33 + tid];
        red[tid] = acc;
    }
    __syncthreads();
    if (tid < 16) {
        float uu = red[tid] + Ash[tid] * red[16 + tid];
        u[tid]  = uu;
        Au[tid] = Ash[tid] * uu;
    }
    __syncthreads();

    // ---- Phase 2: g0[v], g1[v] and score0[m]; zero histograms ----
    float ureg[16], aureg[16];
#pragma unroll
    for (int e = 0; e < 16; e++) { ureg[e] = u[e]; aureg[e] = Au[e]; }

    {
        float g0 = 0.f, g1 = 0.f;
        if (tid < 127) {
            const float4* sr = (const float4*)(sb + tid * 16);
#pragma unroll
            for (int j = 0; j < 4; j++) {
                float4 x4 = sr[j];
                g0 += x4.x*ureg[4*j] + x4.y*ureg[4*j+1] + x4.z*ureg[4*j+2] + x4.w*ureg[4*j+3];
                g1 += x4.x*aureg[4*j] + x4.y*aureg[4*j+1] + x4.z*aureg[4*j+2] + x4.w*aureg[4*j+3];
            }
        }
        g01[tid] = make_float2(g0, g1);
    }
    float s0 = 0.f;
    {
        const float4* mr = (const float4*)(mc + tid * 16);
#pragma unroll
        for (int j = 0; j < 4; j++) {
            float4 x4 = mr[j];
            s0 += x4.x*ureg[4*j] + x4.y*ureg[4*j+1] + x4.z*ureg[4*j+2] + x4.w*ureg[4*j+3];
        }
    }
#pragma unroll 8
    for (int i = 0; i < 67; i++) hist[tid * 67 + i] = 0.f;
    __syncthreads();

    // ---- Phase 3: stream this thread's edge row, score via g01 gathers ----
    int idxs[32];
    {
        bool live = (t < Nc) && (tid < Nc);
        float a = 0.f;
        if (live) a = adj[(b * Nc + t) * Nc + tid];
        if (live && a != 0.f) {
            const float4* er = (const float4*)(edge_fts +
                ((size_t)((b * Nc + t) * Nc + tid)) * Sc);
#pragma unroll
            for (int j = 0; j < 8; j++) {
                float4 x4 = er[j];
                int i0 = (int)x4.x, i1 = (int)x4.y, i2 = (int)x4.z, i3 = (int)x4.w;
                idxs[4*j]   = i0 < 0 ? 0 : (i0 > 127 ? 127 : i0);
                idxs[4*j+1] = i1 < 0 ? 0 : (i1 > 127 ? 127 : i1);
                idxs[4*j+2] = i2 < 0 ? 0 : (i2 > 127 ? 127 : i2);
                idxs[4*j+3] = i3 < 0 ? 0 : (i3 > 127 ? 127 : i3);
            }
        } else {
#pragma unroll
            for (int k = 0; k < 32; k++) idxs[k] = 0;
        }
    }
#pragma unroll
    for (int j = 0; j < 8; j++) {
        unsigned p = (unsigned)idxs[4*j] | ((unsigned)idxs[4*j+1] << 8) |
                     ((unsigned)idxs[4*j+2] << 16) | ((unsigned)idxs[4*j+3] << 24);
        sidxw[tid * 8 + j] = p;
    }
    float score = s0;
#pragma unroll
    for (int k = 0; k < 32; k++) {
        float2 g = g01[idxs[k]];
        score += g.x + Bsh[k] * g.y;
    }

    // ---- Phase 4: softmax over 128 memory slots ----
    {
        float mv = score;
#pragma unroll
        for (int off = 16; off; off >>= 1)
            mv = fmaxf(mv, __shfl_xor_sync(0xFFFFFFFFu, mv, off));
        if (lane == 0) red[wid] = mv;
        __syncthreads();
        float mx = fmaxf(fmaxf(red[0], red[1]), fmaxf(red[2], red[3]));
        float ex = expf(score - mx);
        float smv = ex;
#pragma unroll
        for (int off = 16; off; off >>= 1)
            smv += __shfl_xor_sync(0xFFFFFFFFu, smv, off);
        if (lane == 0) red[4 + wid] = smv;
        __syncthreads();
        float tot = red[4] + red[5] + red[6] + red[7];
        probs[tid] = ex / tot;
    }
    __syncthreads();

    // ---- Phase 5: atomic-free scatter into private histograms ----
    // thread rep = (s, mh): owns hist column rep; scans 64 m-stories.
    if (tid < 64) {
        const int s  = tid & 31;
        const int mh = tid >> 5;
        const int sh = (s & 3) * 8;
        const int wofs = s >> 2;
        for (int mm = 0; mm < 64; mm++) {
            int m = mh * 64 + mm;
            float p = probs[m];
            unsigned w = sidxw[m * 8 + wofs];
            int v = (w >> sh) & 255;
            hist[v * 67 + tid] += p;
        }
    }
    __syncthreads();

    // ---- Phase 6: c0,c1 reduce; o[e]; cross-thread reduce; write x ----
    {
        float c0 = 0.f, c1 = 0.f;
#pragma unroll 8
        for (int rep = 0; rep < 64; rep++) {
            float h = hist[tid * 67 + rep];
            c0 += h;
            c1 = fmaf(Bsh[rep & 31], h, c1);
        }
        float part[16];
        if (tid < 127) {
            const float4* orp = (const float4*)(ob + tid * 16);
#pragma unroll
            for (int j = 0; j < 4; j++) {
                float4 x4 = orp[j];
                part[4*j]   = x4.x * fmaf(Ash[4*j],   c1, c0);
                part[4*j+1] = x4.y * fmaf(Ash[4*j+1], c1, c0);
                part[4*j+2] = x4.z * fmaf(Ash[4*j+2], c1, c0);
                part[4*j+3] = x4.w * fmaf(Ash[4*j+3], c1, c0);
            }
        } else {
#pragma unroll
            for (int e = 0; e < 16; e++) part[e] = 0.f;
        }
#pragma unroll
        for (int e = 0; e < 16; e++) {
#pragma unroll
            for (int off = 16; off; off >>= 1)
                part[e] += __shfl_xor_sync(0xFFFFFFFFu, part[e], off);
        }
        if (lane == 0) {
#pragma unroll
            for (int e = 0; e < 16; e++) upart[wid * 16 + e] = part[e];
        }
    }
    __syncthreads();
    if (tid < 16) {
        float o = upart[tid] + upart[16 + tid] + upart[32 + tid] + upart[48 + tid];
        g_xbuf[bt * 16 + tid] = u[tid] + o;
    }
}

// ---------------------------------------------------------------------------
// Kernel 2: ret = relu((u+o) @ W_out) @ W_fin, 4 bt per pass (quad-blocked).
// ---------------------------------------------------------------------------
__global__ __launch_bounds__(128) void memnet_gemm(
    const float* __restrict__ W_out,   // [16,128]
    const float* __restrict__ W_fin)   // [128,128]
{
    extern __shared__ float sm[];
    float* Wo  = sm;            // 2048
    float* Wf  = Wo + 2048;     // 16384
    float* xs  = Wf + 16384;    // 64
    float* hsT = xs + 64;       // [128][4]

    const int tid = threadIdx.x;
    for (int i = tid; i < 2048; i += 128)  Wo[i] = W_out[i];
    for (int i = tid; i < 16384; i += 128) Wf[i] = W_fin[i];
    __syncthreads();

    for (int g = blockIdx.x; g < BTc / 4; g += gridDim.x) {
        if (tid < 64) xs[tid] = g_xbuf[g * 64 + tid];
        __syncthreads();
#pragma unroll
        for (int q = 0; q < 4; q++) {
            float a = 0.f;
#pragma unroll
            for (int e = 0; e < 16; e++)
                a += xs[q * 16 + e] * Wo[e * 128 + tid];
            hsT[tid * 4 + q] = fmaxf(a, 0.f);
        }
        __syncthreads();
        float a0 = 0.f, a1 = 0.f, a2 = 0.f, a3 = 0.f;
#pragma unroll 8
        for (int l = 0; l < 128; l++) {
            float wv = Wf[l * 128 + tid];
            float4 hv = ((const float4*)hsT)[l];
            a0 = fmaf(hv.x, wv, a0);
            a1 = fmaf(hv.y, wv, a1);
            a2 = fmaf(hv.z, wv, a2);
            a3 = fmaf(hv.w, wv, a3);
        }
        g_ret[(g * 4 + 0) * 128 + tid] = a0;
        g_ret[(g * 4 + 1) * 128 + tid] = a1;
        g_ret[(g * 4 + 2) * 128 + tid] = a2;
        g_ret[(g * 4 + 3) * 128 + tid] = a3;
        __syncthreads();
    }
}

// ---------------------------------------------------------------------------
// Kernel 3: out[b,i,:] = ret[b,i,:] + ret[b,127,:]  (float4 vectorized)
// ---------------------------------------------------------------------------
__global__ void memnet_final(float4* __restrict__ out)
{
    const int total4 = Bc * Nc * Vc / 4;   // 65024
    int idx4 = blockIdx.x * blockDim.x + threadIdx.x;
    if (idx4 < total4) {
        int c   = idx4 & 31;     // float4 index within the 128-wide row
        int rem = idx4 >> 5;
        int i   = rem % Nc;
        int b   = rem / Nc;
        const float4* r = (const float4*)g_ret;
        float4 a = r[((b << 7) + i) * 32 + c];
        float4 g = r[((b << 7) + 127) * 32 + c];
        out[idx4] = make_float4(a.x + g.x, a.y + g.y, a.z + g.z, a.w + g.w);
    }
}

extern "C" void kernel_launch(void* const* d_in, const int* in_sizes, int n_in,
                              void* d_out, int out_size)
{
    const float* node_fts  = (const float*)d_in[0];
    const float* edge_fts  = (const float*)d_in[1];
    const float* graph_fts = (const float*)d_in[2];
    const float* adj       = (const float*)d_in[3];
    // d_in[4] hidden: unused
    const float* enc       = (const float*)d_in[5];
    const float* qb        = (const float*)d_in[6];
    const float* sb        = (const float*)d_in[7];
    const float* ob        = (const float*)d_in[8];
    const float* mc        = (const float*)d_in[9];
    // d_in[10] W_int: unused (num_hops == 1)
    const float* W_out     = (const float*)d_in[11];
    const float* W_fin     = (const float*)d_in[12];
    float4* out = (float4*)d_out;

    const int SM2 = (2048 + 16384 + 64 + 512) * 4;
    cudaFuncSetAttribute(memnet_main, cudaFuncAttributeMaxDynamicSharedMemorySize, SMEM_MAIN);
    cudaFuncSetAttribute(memnet_gemm, cudaFuncAttributeMaxDynamicSharedMemorySize, SM2);

    memnet_main<<<BTc, 128, SMEM_MAIN>>>(node_fts, edge_fts, graph_fts, adj, enc,
                                         qb, sb, ob, mc);
    memnet_gemm<<<256, 128, SM2>>>(W_out, W_fin);
    memnet_final<<<(Bc * Nc * Vc / 4 + 255) / 256, 256>>>(out);
}